// round 10
// baseline (speedup 1.0000x reference)
#include <cuda_runtime.h>
#include <cuda_bf16.h>

// LocalLoadBalancingLoss: B=65536, T=792, D=99, L=16.
// loss = mean_b[ var_{ddof=1}(u_b) + 0.5 * max(u_b) ], u = linkTraffic/(cap+1e-8)
//
// R10: single fused kernel. 4096 blocks x 16 rows, 512 thr, 3 blocks/SM
// (40 regs -> ILP). Each block redundantly builds the link-sorted packed CSR in
// its own smem while cp.async stages the tile (build hides DRAM latency).
// Phase B: warp = link, half-warp = segment half, lane = row; all LDS
// conflict-free (pred stride 793, dem stride 99). Fused deterministic reduction.

#define NUM_T 792
#define NUM_D 99
#define NUM_L 16
#define ROWS 16
#define THREADS 512
#define PST 793                 // odd stride -> conflict-free LDS across rows
#define MAX_BLOCKS 4096

__device__ float    g_partials[MAX_BLOCKS];
__device__ unsigned g_done;

__device__ __forceinline__ void cpa4(unsigned dst, const float* src) {
    asm volatile("cp.async.ca.shared.global [%0], [%1], 4;" :: "r"(dst), "l"(src));
}
__device__ __forceinline__ void cpa16(unsigned dst, const float* src) {
    asm volatile("cp.async.cg.shared.global [%0], [%1], 16;" :: "r"(dst), "l"(src));
}

__global__ __launch_bounds__(THREADS, 3)
void llb_kernel(const float* __restrict__ pred,
                const float* __restrict__ dem,
                const int*   __restrict__ t2l,
                const float* __restrict__ cap,
                float* __restrict__ out,
                float inv_batch) {
    extern __shared__ float smem[];
    float*    sp   = smem;                          // [16][793] pred tile
    float*    sd   = sp + ROWS * PST;               // [16][99] dem; later su[16][17]
    unsigned* six  = (unsigned*)(sd + ROWS * NUM_D);// [792] packed (pred_off<<16|dem_off)
    int*      scnt = (int*)(six + NUM_T);           // [25][16] counts -> prefix
    int*      soff = scnt + 25 * NUM_L;             // [17] link offsets
    int*      sfl  = soff + 17;

    const int tid  = threadIdx.x;
    const int w    = tid >> 5;           // warp id == link in phase B
    const int lane = tid & 31;
    const int part = lane >> 4;          // segment half
    const int r    = lane & 15;          // row

    // ---- issue stage-in (all groups, one commit) ----
    const long long tile = blockIdx.x;
    const float* gp = pred + tile * (ROWS * NUM_T);
    const float* gd = dem  + tile * (ROWS * NUM_D);
    const unsigned spA = (unsigned)__cvta_generic_to_shared(sp);
    const unsigned sdA = (unsigned)__cvta_generic_to_shared(sd);

    #pragma unroll
    for (int k = 0; k < 25; k++) {
        int i = tid + k * THREADS;
        if (i < ROWS * NUM_T) {
            int rr = (unsigned)i / NUM_T;            // smem idx = i + rr (stride 793)
            cpa4(spA + 4u * (unsigned)(i + rr), gp + i);
        }
    }
    if (tid < (ROWS * NUM_D) / 4)                    // 1584 floats = 396 x 16B
        cpa16(sdA + 16u * (unsigned)tid, gd + 4 * tid);
    asm volatile("cp.async.commit_group;");

    // ---- CSR build (redundant per block; overlaps the DRAM wait) ----
    if (tid < 25 * NUM_L) scnt[tid] = 0;
    __syncthreads();

    // round 1: tunnels 0..511 (16 full warps)
    const int l1 = t2l[tid];
    unsigned m1 = __match_any_sync(0xFFFFFFFFu, l1);
    const int rank1 = __popc(m1 & ((1u << lane) - 1u));
    if (lane == (__ffs(m1) - 1)) scnt[w * NUM_L + l1] = __popc(m1);

    // round 2: tunnels 512..791 (280 threads; idle lanes -> unique singletons)
    const int  t2   = 512 + tid;
    const bool act2 = (t2 < NUM_T);
    const int  l2   = act2 ? t2l[t2] : 0;
    const int  v2   = act2 ? l2 : (100 + lane);
    unsigned m2 = __match_any_sync(0xFFFFFFFFu, v2);
    const int rank2 = __popc(m2 & ((1u << lane) - 1u));
    if (act2 && lane == (__ffs(m2) - 1)) scnt[(16 + w) * NUM_L + l2] = __popc(m2);
    __syncthreads();

    if (tid < NUM_L) {                   // exclusive prefix over 25 slots per link
        int a = 0;
        for (int s = 0; s < 25; s++) {
            int c = scnt[s * NUM_L + tid];
            scnt[s * NUM_L + tid] = a;
            a += c;
        }
        soff[tid] = a;                   // per-link total (temporarily)
    }
    __syncthreads();
    if (tid == 0) {                      // serial 16-step prefix, fully hidden
        int a = 0;
        #pragma unroll
        for (int l = 0; l < NUM_L; l++) { int c = soff[l]; soff[l] = a; a += c; }
        soff[NUM_L] = a;                 // == 792
    }
    __syncthreads();

    // write packed entries (byte offsets): ascending t within each link
    six[soff[l1] + scnt[w * NUM_L + l1] + rank1] =
        ((unsigned)(tid * 4) << 16) | (unsigned)((tid >> 3) * 4);
    if (act2)
        six[soff[l2] + scnt[(16 + w) * NUM_L + l2] + rank2] =
            ((unsigned)(t2 * 4) << 16) | (unsigned)((t2 >> 3) * 4);
    __syncthreads();

    // ---- per-warp segment metadata ----
    const int   len   = soff[w + 1] - soff[w];
    const int   len0  = (len + 1) >> 1;
    const int   mybeg = soff[w] + (part ? len0 : 0);
    const int   mycnt = part ? (len - len0) : len0;
    const float invc  = 1.0f / (cap[w] + 1e-8f);

    asm volatile("cp.async.wait_group 0;");
    __syncthreads();

    // ---- phase B: half-warp walks its half-segment, lane = row ----
    const char* pr = (const char*)(sp + r * PST);
    const char* dm = (const char*)(sd + r * NUM_D);

    float s0 = 0.f, s1 = 0.f;
    int i = 0;
    for (; i + 1 < mycnt; i += 2) {
        unsigned p0 = six[mybeg + i];
        unsigned p1 = six[mybeg + i + 1];
        s0 += *(const float*)(pr + (p0 >> 16)) * *(const float*)(dm + (p0 & 0xFFFFu));
        s1 += *(const float*)(pr + (p1 >> 16)) * *(const float*)(dm + (p1 & 0xFFFFu));
    }
    if (i < mycnt) {
        unsigned p0 = six[mybeg + i];
        s0 += *(const float*)(pr + (p0 >> 16)) * *(const float*)(dm + (p0 & 0xFFFFu));
    }
    float u = (s0 + s1) * invc;
    u += __shfl_down_sync(0xFFFFFFFFu, u, 16);       // combine segment halves

    __syncthreads();                     // all sd reads done -> overlay su
    float* su = sd;                      // [16 links][17]
    if (part == 0) su[w * 17 + r] = u;
    __syncthreads();

    // ---- per-row stats: warp 0, lanes 0-15 (row = lane) ----
    float pv = 0.f;
    if (w == 0 && part == 0) {
        float sum = 0.f, mx = -1e30f;
        #pragma unroll
        for (int l = 0; l < NUM_L; l++) {
            float x = su[l * 17 + r];
            sum += x;
            mx = fmaxf(mx, x);
        }
        const float mean = sum * (1.0f / NUM_L);
        float var = 0.f;
        #pragma unroll
        for (int l = 0; l < NUM_L; l++) {
            float d = su[l * 17 + r] - mean;
            var += d * d;
        }
        var *= (1.0f / (NUM_L - 1));     // ddof = 1
        pv = var + 0.5f * mx;
        #pragma unroll
        for (int o = 8; o > 0; o >>= 1)
            pv += __shfl_down_sync(0x0000FFFFu, pv, o);
    }
    if (tid == 0) g_partials[blockIdx.x] = pv;

    // ---- fused deterministic reduction: last block, fixed-order tree ----
    __threadfence();
    if (tid == 0) {
        unsigned n = atomicAdd(&g_done, 1u);
        sfl[0] = (n == (unsigned)(gridDim.x - 1)) ? 1 : 0;
    }
    __syncthreads();
    if (sfl[0]) {
        __threadfence();
        float v = 0.f;
        #pragma unroll
        for (int k = 0; k < MAX_BLOCKS / THREADS; k++)
            v += g_partials[tid + k * THREADS];      // fixed order per thread
        float* rb = sp;                              // reuse smem
        rb[tid] = v;
        __syncthreads();
        #pragma unroll
        for (int s = THREADS / 2; s > 0; s >>= 1) {
            if (tid < s) rb[tid] += rb[tid + s];     // fixed pairing -> deterministic
            __syncthreads();
        }
        if (tid == 0) {
            out[0] = rb[0] * inv_batch;
            g_done = 0;                              // reset for next graph replay
        }
    }
}

extern "C" void kernel_launch(void* const* d_in, const int* in_sizes, int n_in,
                              void* d_out, int out_size) {
    const float* pred = (const float*)d_in[0];   // [B, 792]
    const float* dem  = (const float*)d_in[1];   // [B, 99]
    const int*   t2l  = (const int*)d_in[2];     // [792]
    const float* cap  = (const float*)d_in[3];   // [16]
    float* out = (float*)d_out;

    const int B = in_sizes[1] / NUM_D;           // 65536
    const int ntiles = B / ROWS;                 // 4096

    // floats: 16*793 + 16*99 = 14272; + 792 idx + 400 cnt + 17 off + 1 flag ints
    const int smem_bytes = (ROWS * PST + ROWS * NUM_D) * (int)sizeof(float)
                         + (NUM_T + 25 * NUM_L + 17 + 1) * (int)sizeof(int); // 61928
    static bool attr_set = false;
    if (!attr_set) {
        cudaFuncSetAttribute(llb_kernel,
                             cudaFuncAttributeMaxDynamicSharedMemorySize, smem_bytes);
        attr_set = true;
    }

    llb_kernel<<<ntiles, THREADS, smem_bytes>>>(pred, dem, t2l, cap, out,
                                                1.0f / (float)B);
}